// round 1
// baseline (speedup 1.0000x reference)
#include <cuda_runtime.h>

#define THREADS 256

__global__ void __launch_bounds__(256) graphres_kernel(
    const float* __restrict__ x,
    const float* __restrict__ A_param,
    const float* __restrict__ W1,
    const float* __restrict__ b1,
    const float* __restrict__ W2,
    const float* __restrict__ b2,
    float* __restrict__ out,
    int nvec4)
{
    // Small working tables
    __shared__ float  sA[36];          // softmax(A_param)
    __shared__ float  st[48];          // sorted knots, padded with +INF
    __shared__ float2 sac[33];         // (slope, intercept) per segment
    __shared__ float  s_t[32], s_dA[32], s_dC[32];
    __shared__ float  so_dA[32], so_dC[32];
    // Lane-replicated tables (bank-conflict-free gathers)
    __shared__ float  rep_k[48 * 32];
    __shared__ float2 rep_ac[33 * 32];

    const int tid = threadIdx.x;
    const float INFF = __int_as_float(0x7f800000);

    // ---- preamble: softmax rows (threads 0..5) ----
    if (tid < 6) {
        float v[6];
        float mx = -3.4e38f;
        #pragma unroll
        for (int n = 0; n < 6; ++n) { v[n] = A_param[tid * 6 + n]; mx = fmaxf(mx, v[n]); }
        float s = 0.f;
        #pragma unroll
        for (int n = 0; n < 6; ++n) { v[n] = expf(v[n] - mx); s += v[n]; }
        float inv = 1.f / s;
        #pragma unroll
        for (int n = 0; n < 6; ++n) sA[tid * 6 + n] = v[n] * inv;
    }
    // ---- knots + crossing deltas (threads 0..31) ----
    if (tid < 32) {
        float w1 = W1[tid], bb = b1[tid], w2 = W2[tid];
        float t, dA, dC;
        if (w1 > 0.f)      { t = -bb / w1; dA =  w1 * w2; dC =  bb * w2; }
        else if (w1 < 0.f) { t = -bb / w1; dA = -(w1 * w2); dC = -(bb * w2); }
        else               { t = INFF;     dA = 0.f;       dC = 0.f; }
        s_t[tid] = t; s_dA[tid] = dA; s_dC[tid] = dC;
    }
    if (tid >= 32 && tid < 48) st[tid] = INFF;   // pad region for search ladder
    __syncthreads();

    // ---- rank-sort (stable) the 32 knots ----
    if (tid < 32) {
        float t = s_t[tid];
        int r = 0;
        #pragma unroll
        for (int j = 0; j < 32; ++j) {
            float tj = s_t[j];
            r += (tj < t || (tj == t && j < tid)) ? 1 : 0;
        }
        st[r] = t; so_dA[r] = s_dA[tid]; so_dC[r] = s_dC[tid];
    }
    __syncthreads();

    // ---- prefix: base segment (y -> -inf) then accumulate crossings ----
    if (tid == 0) {
        float a = 0.f, c = b2[0];
        for (int k = 0; k < 32; ++k) {
            float w1 = W1[k];
            if (w1 < 0.f)       { a += w1 * W2[k]; c += b1[k] * W2[k]; }
            else if (w1 == 0.f) { c += fmaxf(b1[k], 0.f) * W2[k]; }
        }
        sac[0] = make_float2(a, c);
        for (int j = 0; j < 32; ++j) {
            a += so_dA[j]; c += so_dC[j];
            sac[j + 1] = make_float2(a, c);
        }
    }
    __syncthreads();

    // ---- replicate tables per lane; load A into registers ----
    for (int i = tid; i < 48 * 32; i += THREADS) rep_k[i]  = st[i >> 5];
    for (int i = tid; i < 33 * 32; i += THREADS) rep_ac[i] = sac[i >> 5];
    float Areg[36];
    #pragma unroll
    for (int i = 0; i < 36; ++i) Areg[i] = sA[i];
    const float k31 = st[31];
    const float k15 = st[15];
    __syncthreads();

    const int lane = tid & 31;
    const float*  kp  = rep_k  + lane;
    const float2* acp = rep_ac + lane;

    const float4* xin  = (const float4*)x;
    float4*       xout = (float4*)out;
    const int gt   = blockIdx.x * THREADS + tid;
    const int base = gt * 12;   // 12 float4 = 8 rows per thread

    #pragma unroll 1
    for (int it = 0; it < 4; ++it) {
        const int b0 = base + it * 3;           // 3 float4 = 2 rows
        if (b0 + 3 > nvec4) break;
        float4 v0 = xin[b0 + 0];
        float4 v1 = xin[b0 + 1];
        float4 v2 = xin[b0 + 2];
        float xr[12] = { v0.x, v0.y, v0.z, v0.w,
                         v1.x, v1.y, v1.z, v1.w,
                         v2.x, v2.y, v2.z, v2.w };
        float ov[12];
        #pragma unroll
        for (int r = 0; r < 2; ++r) {
            const float* xx = xr + r * 6;
            float*       oo = ov + r * 6;
            #pragma unroll
            for (int m = 0; m < 6; ++m) {
                // y = (A x)[m], two parallel FMA chains
                float ya = Areg[m * 6 + 0] * xx[0];
                float yb = Areg[m * 6 + 1] * xx[1];
                ya = fmaf(Areg[m * 6 + 2], xx[2], ya);
                yb = fmaf(Areg[m * 6 + 3], xx[3], yb);
                ya = fmaf(Areg[m * 6 + 4], xx[4], ya);
                yb = fmaf(Areg[m * 6 + 5], xx[5], yb);
                float y = ya + yb;

                // branchless lower-bound over 32 sorted knots (+INF padded)
                int c = (y > k31) ? 32 : 0;
                float l2 = (c == 0) ? k15 : INFF;
                if (y > l2)                 c += 16;
                if (y > kp[(c + 7) << 5])   c += 8;
                if (y > kp[(c + 3) << 5])   c += 4;
                if (y > kp[(c + 1) << 5])   c += 2;
                if (y > kp[(c    ) << 5])   c += 1;

                float2 ac = acp[c << 5];
                oo[m] = fmaf(ac.x, y, ac.y) + xx[m];
            }
        }
        float4 o0 = make_float4(ov[0], ov[1], ov[2],  ov[3]);
        float4 o1 = make_float4(ov[4], ov[5], ov[6],  ov[7]);
        float4 o2 = make_float4(ov[8], ov[9], ov[10], ov[11]);
        xout[b0 + 0] = o0;
        xout[b0 + 1] = o1;
        xout[b0 + 2] = o2;
    }
}

extern "C" void kernel_launch(void* const* d_in, const int* in_sizes, int n_in,
                              void* d_out, int out_size)
{
    const float* x  = (const float*)d_in[0];
    const float* Ap = (const float*)d_in[1];
    const float* W1 = (const float*)d_in[2];
    const float* b1 = (const float*)d_in[3];
    const float* W2 = (const float*)d_in[4];
    const float* b2 = (const float*)d_in[5];
    float* out = (float*)d_out;

    int nvec4 = out_size / 4;                       // total float4s (B*N/4)
    int threads_total = (nvec4 + 11) / 12;          // 12 float4 per thread
    int grid = (threads_total + THREADS - 1) / THREADS;
    graphres_kernel<<<grid, THREADS>>>(x, Ap, W1, b1, W2, b2, out, nvec4);
}